// round 1
// baseline (speedup 1.0000x reference)
#include <cuda_runtime.h>
#include <math.h>

#define An 32
#define Bn 128
#define Nn 4096
#define Tt 5
#define Hh 4
#define DHh 64
#define Dd 256
#define Ll 64

// Scratch: ping-pong feature buffers (T*N*D floats each = 21MB)
__device__ float g_h1[Tt * Nn * Dd];
__device__ float g_h2[Tt * Nn * Dd];

// ---------------------------------------------------------------------------
// Fused GAT layer: one CTA per (t, block). 256 threads.
//   h = x @ W            (32 x FIN) @ (FIN x 256)
//   al_s/al_d per head, leaky_relu scores, per-dst softmax over 32 srcs
//   out[d] = sum_s alpha[d,s] * h[s]  (per head), + bias, ReLU
// STAGE 1: x = param (node_feats), W in smem, out -> g_h1
// STAGE 2: x = g_h1, W from global(L2), out -> g_h2
// ---------------------------------------------------------------------------
template <int FIN, int STAGE>
__global__ __launch_bounds__(256)
void gat_kernel(const float* __restrict__ x_in,
                const float* __restrict__ W,
                const float* __restrict__ asrc,
                const float* __restrict__ adst,
                const float* __restrict__ bias)
{
    extern __shared__ float sm[];
    const int HSTRIDE = 260;                 // 256 + 4 pad (float4-friendly, kills bank conflicts)
    float* h_sm  = sm;                       // 32*260 = 8320
    float* alpha = h_sm + 32 * HSTRIDE;      // 4*32*33 = 4224 (stride 33 -> conflict-free rows)
    float* x_sm  = alpha + 4 * 32 * 33;      // 32*FIN
    float* als   = x_sm + 32 * FIN;          // 128
    float* ald   = als + 128;                // 128
    float* W_sm  = ald + 128;                // FIN*256 (stage 1 only)

    const int tid = threadIdx.x;
    const int t   = blockIdx.x / Bn;
    const int bb  = blockIdx.x % Bn;

    const float* xsrc = (STAGE == 1) ? x_in : g_h1;
    float*       outp = (STAGE == 1) ? g_h1 : g_h2;

    const float* xblk = xsrc + ((size_t)t * Nn + (size_t)bb * An) * FIN;

    // load x tile (coalesced)
    for (int i = tid; i < 32 * FIN; i += 256) x_sm[i] = xblk[i];
    if (STAGE == 1) {
        for (int i = tid; i < FIN * Dd; i += 256) W_sm[i] = W[i];
    }
    __syncthreads();

    // ---- h = x @ W : thread owns column c for all 32 rows ----
    {
        const int c = tid;
        float acc[32];
        #pragma unroll
        for (int r = 0; r < 32; r++) acc[r] = 0.f;

        for (int k4 = 0; k4 < FIN; k4 += 4) {
            float w0, w1, w2, w3;
            if (STAGE == 1) {
                w0 = W_sm[(k4 + 0) * Dd + c];
                w1 = W_sm[(k4 + 1) * Dd + c];
                w2 = W_sm[(k4 + 2) * Dd + c];
                w3 = W_sm[(k4 + 3) * Dd + c];
            } else {
                w0 = W[(size_t)(k4 + 0) * Dd + c];
                w1 = W[(size_t)(k4 + 1) * Dd + c];
                w2 = W[(size_t)(k4 + 2) * Dd + c];
                w3 = W[(size_t)(k4 + 3) * Dd + c];
            }
            #pragma unroll
            for (int r = 0; r < 32; r++) {
                float4 xv = *reinterpret_cast<const float4*>(&x_sm[r * FIN + k4]); // broadcast
                acc[r] = fmaf(xv.x, w0, acc[r]);
                acc[r] = fmaf(xv.y, w1, acc[r]);
                acc[r] = fmaf(xv.z, w2, acc[r]);
                acc[r] = fmaf(xv.w, w3, acc[r]);
            }
        }
        #pragma unroll
        for (int r = 0; r < 32; r++) h_sm[r * HSTRIDE + c] = acc[r];
    }
    __syncthreads();

    // ---- attention logits per (node, head) ----
    if (tid < 128) {
        const int r = tid & 31;
        const int head = tid >> 5;
        const float* hrow = &h_sm[r * HSTRIDE + head * DHh];
        const float* as = &asrc[head * DHh];
        const float* ad = &adst[head * DHh];
        float s1 = 0.f, s2 = 0.f;
        #pragma unroll 8
        for (int j = 0; j < DHh; j++) {
            float hv = hrow[j];
            s1 = fmaf(hv, as[j], s1);
            s2 = fmaf(hv, ad[j], s2);
        }
        als[head * 32 + r] = s1;
        ald[head * 32 + r] = s2;
    }
    __syncthreads();

    // ---- softmax per (dst d, head) over 32 srcs ----
    if (tid < 128) {
        const int d = tid & 31;
        const int head = tid >> 5;
        float* arow = &alpha[head * (32 * 33) + d * 33];
        const float adv = ald[head * 32 + d];
        float m = -1e30f;
        #pragma unroll
        for (int s = 0; s < 32; s++) {
            float e = als[head * 32 + s] + adv;
            e = (e >= 0.f) ? e : 0.2f * e;      // leaky_relu slope 0.2
            arow[s] = e;
            m = fmaxf(m, e);
        }
        float z = 0.f;
        #pragma unroll
        for (int s = 0; s < 32; s++) {
            float p = expf(arow[s] - m);
            arow[s] = p;
            z += p;
        }
        const float inv = 1.f / (z + 1e-16f);
        #pragma unroll
        for (int s = 0; s < 32; s++) arow[s] *= inv;
    }
    __syncthreads();

    // ---- aggregation: out[d, c] = sum_s alpha[head(c)][d][s] * h[s][c] ----
    {
        const int lane64 = tid & 63;           // float4 column slot 0..63
        const int col    = lane64 * 4;         // output column 0..252
        const int head   = lane64 >> 4;        // col / 64
        const int d0     = (tid >> 6) * 8;     // 8 dst rows per thread

        const float4* h4 = reinterpret_cast<const float4*>(h_sm);
        const float* arow0 = &alpha[head * (32 * 33)];

        float4 acc4[8];
        #pragma unroll
        for (int dd = 0; dd < 8; dd++) acc4[dd] = make_float4(0.f, 0.f, 0.f, 0.f);

        for (int s = 0; s < 32; s++) {
            float4 hv = h4[s * (HSTRIDE / 4) + lane64];
            #pragma unroll
            for (int dd = 0; dd < 8; dd++) {
                float a = arow0[(d0 + dd) * 33 + s];
                acc4[dd].x = fmaf(a, hv.x, acc4[dd].x);
                acc4[dd].y = fmaf(a, hv.y, acc4[dd].y);
                acc4[dd].z = fmaf(a, hv.z, acc4[dd].z);
                acc4[dd].w = fmaf(a, hv.w, acc4[dd].w);
            }
        }

        float4 bv = *reinterpret_cast<const float4*>(&bias[col]);
        float* outblk = outp + ((size_t)t * Nn + (size_t)bb * An) * Dd;
        #pragma unroll
        for (int dd = 0; dd < 8; dd++) {
            int d = d0 + dd;
            float4 o;
            o.x = fmaxf(acc4[dd].x + bv.x, 0.f);
            o.y = fmaxf(acc4[dd].y + bv.y, 0.f);
            o.z = fmaxf(acc4[dd].z + bv.z, 0.f);
            o.w = fmaxf(acc4[dd].w + bv.w, 0.f);
            *reinterpret_cast<float4*>(&outblk[d * Dd + col]) = o;
        }
    }
}

// ---------------------------------------------------------------------------
// Transformer over T=5 (last query row only) + output heads. One CTA per b.
// ---------------------------------------------------------------------------
__global__ __launch_bounds__(256)
void head_kernel(const float* __restrict__ wq, const float* __restrict__ bq,
                 const float* __restrict__ wk, const float* __restrict__ bk,
                 const float* __restrict__ wv, const float* __restrict__ bv,
                 const float* __restrict__ wo, const float* __restrict__ bo,
                 const float* __restrict__ lm_w, const float* __restrict__ lm_b,
                 const float* __restrict__ lv_w, const float* __restrict__ lv_b,
                 const float* __restrict__ ap_w, const float* __restrict__ ap_b,
                 const float* __restrict__ bh_w, const float* __restrict__ bh_b,
                 float* __restrict__ out)
{
    __shared__ float seq[Tt][Dd];
    __shared__ float ksm[Tt][Dd];
    __shared__ float vsm[Tt][Dd];
    __shared__ float qsm[Dd];
    __shared__ float ctx[Dd];
    __shared__ float feat[Dd];
    __shared__ float musm[Ll];
    __shared__ float attn[Hh][Tt];

    const int b = blockIdx.x;
    const int tid = threadIdx.x;
    const int c = tid;

    // seq[b, t, :] = feats[t, b*32, :]  (ego node of each block)
    #pragma unroll
    for (int t = 0; t < Tt; t++)
        seq[t][tid] = g_h2[((size_t)t * Nn + (size_t)b * An) * Dd + tid];
    __syncthreads();

    // q (last row), k, v for all t — thread owns column c
    {
        float aq = 0.f;
        float ak[Tt] = {0, 0, 0, 0, 0};
        float av[Tt] = {0, 0, 0, 0, 0};
        #pragma unroll 4
        for (int k = 0; k < Dd; k++) {
            float wqv = wq[(size_t)k * Dd + c];
            float wkv = wk[(size_t)k * Dd + c];
            float wvv = wv[(size_t)k * Dd + c];
            aq = fmaf(seq[Tt - 1][k], wqv, aq);
            #pragma unroll
            for (int t = 0; t < Tt; t++) {
                float sv = seq[t][k];
                ak[t] = fmaf(sv, wkv, ak[t]);
                av[t] = fmaf(sv, wvv, av[t]);
            }
        }
        qsm[c] = aq + bq[c];
        #pragma unroll
        for (int t = 0; t < Tt; t++) {
            ksm[t][c] = ak[t] + bk[c];
            vsm[t][c] = av[t] + bv[c];
        }
    }
    __syncthreads();

    // scores for last query row (causal: all 5 keys allowed)
    if (tid < Hh * Tt) {
        const int head = tid / Tt;
        const int t = tid % Tt;
        float s = 0.f;
        #pragma unroll 8
        for (int j = 0; j < DHh; j++)
            s = fmaf(qsm[head * DHh + j], ksm[t][head * DHh + j], s);
        attn[head][t] = s * 0.125f;   // / sqrt(64)
    }
    __syncthreads();

    if (tid < Hh) {
        float m = -1e30f;
        #pragma unroll
        for (int t = 0; t < Tt; t++) m = fmaxf(m, attn[tid][t]);
        float z = 0.f;
        #pragma unroll
        for (int t = 0; t < Tt; t++) { float p = expf(attn[tid][t] - m); attn[tid][t] = p; z += p; }
        float inv = 1.f / z;
        #pragma unroll
        for (int t = 0; t < Tt; t++) attn[tid][t] *= inv;
    }
    __syncthreads();

    // ctx (last row only)
    {
        const int head = c >> 6;
        float a = 0.f;
        #pragma unroll
        for (int t = 0; t < Tt; t++) a = fmaf(attn[head][t], vsm[t][c], a);
        ctx[c] = a;
    }
    __syncthreads();

    // feat = ctx @ wo + bo
    {
        float f = bo[c];
        #pragma unroll 4
        for (int k = 0; k < Dd; k++) f = fmaf(ctx[k], wo[(size_t)k * Dd + c], f);
        feat[c] = f;
    }
    __syncthreads();

    float* ob = out + (size_t)b * 400;

    if (tid < 64) {
        float m = lm_b[tid];
        #pragma unroll 4
        for (int k = 0; k < Dd; k++) m = fmaf(feat[k], lm_w[(size_t)k * Ll + tid], m);
        musm[tid] = m;
        ob[tid] = m;                          // mu -> [0,64)
    } else if (tid < 128) {
        const int cc = tid - 64;
        float m = lv_b[cc];
        #pragma unroll 4
        for (int k = 0; k < Dd; k++) m = fmaf(feat[k], lv_w[(size_t)k * Ll + cc], m);
        ob[64 + cc] = m;                      // logvar -> [64,128)
    } else if (tid < 144) {
        const int cc = tid - 128;
        float m = bh_b[cc];
        #pragma unroll 4
        for (int k = 0; k < Dd; k++) m = fmaf(feat[k], bh_w[(size_t)k * 16 + cc], m);
        ob[384 + cc] = m;                     // belief -> [384,400)
    }
    __syncthreads();

    // act = mu @ ap_w + ap_b -> [128,384)
    {
        float a = ap_b[c];
        #pragma unroll 8
        for (int k = 0; k < Ll; k++) a = fmaf(musm[k], ap_w[(size_t)k * Dd + c], a);
        ob[128 + c] = a;
    }
}

// ---------------------------------------------------------------------------
extern "C" void kernel_launch(void* const* d_in, const int* in_sizes, int n_in,
                              void* d_out, int out_size)
{
    const float* node_feats = (const float*)d_in[0];
    // d_in[1] = edge_index (block structure is fixed; not needed)
    const float* gat1_w  = (const float*)d_in[2];
    const float* gat1_as = (const float*)d_in[3];
    const float* gat1_ad = (const float*)d_in[4];
    const float* gat1_b  = (const float*)d_in[5];
    const float* gat2_w  = (const float*)d_in[6];
    const float* gat2_as = (const float*)d_in[7];
    const float* gat2_ad = (const float*)d_in[8];
    const float* gat2_b  = (const float*)d_in[9];
    const float* wq = (const float*)d_in[10];
    const float* bq = (const float*)d_in[11];
    const float* wk = (const float*)d_in[12];
    const float* bk = (const float*)d_in[13];
    const float* wv = (const float*)d_in[14];
    const float* bv = (const float*)d_in[15];
    const float* wo = (const float*)d_in[16];
    const float* bo = (const float*)d_in[17];
    const float* lm_w = (const float*)d_in[18];
    const float* lm_b = (const float*)d_in[19];
    const float* lv_w = (const float*)d_in[20];
    const float* lv_b = (const float*)d_in[21];
    const float* ap_w = (const float*)d_in[22];
    const float* ap_b = (const float*)d_in[23];
    const float* bh_w = (const float*)d_in[24];
    const float* bh_b = (const float*)d_in[25];
    float* out = (float*)d_out;

    // dynamic smem sizes (floats): h(32*260) + alpha(4*32*33) + x(32*FIN) + als/ald(256) [+ W]
    const size_t sm1 = (size_t)(8320 + 4224 + 32 * 24 + 256 + 24 * 256) * sizeof(float);   // 78848 B
    const size_t sm2 = (size_t)(8320 + 4224 + 32 * 256 + 256) * sizeof(float);             // 83968 B

    cudaFuncSetAttribute(gat_kernel<24, 1>,  cudaFuncAttributeMaxDynamicSharedMemorySize, (int)sm1);
    cudaFuncSetAttribute(gat_kernel<256, 2>, cudaFuncAttributeMaxDynamicSharedMemorySize, (int)sm2);

    gat_kernel<24, 1><<<Tt * Bn, 256, sm1>>>(node_feats, gat1_w, gat1_as, gat1_ad, gat1_b);
    gat_kernel<256, 2><<<Tt * Bn, 256, sm2>>>(nullptr, gat2_w, gat2_as, gat2_ad, gat2_b);
    head_kernel<<<Bn, 256>>>(wq, bq, wk, bk, wv, bv, wo, bo,
                             lm_w, lm_b, lv_w, lv_b, ap_w, ap_b, bh_w, bh_b, out);
}

// round 2
// speedup vs baseline: 1.1576x; 1.1576x over previous
#include <cuda_runtime.h>
#include <math.h>

#define An 32
#define Bn 128
#define Nn 4096
#define Tt 5
#define Hh 4
#define DHh 64
#define Dd 256
#define Ll 64

typedef unsigned long long ull;

// Scratch: ping-pong feature buffers
__device__ float g_h1[Tt * Nn * Dd];
__device__ float g_h2[Tt * Nn * Dd];

// ---- packed f32x2 helpers (SASS FFMA2 path; ptxas won't emit it from C++) ----
__device__ __forceinline__ ull pack2(float lo, float hi) {
    ull r;
    asm("mov.b64 %0, {%1, %2};" : "=l"(r) : "f"(lo), "f"(hi));
    return r;
}
__device__ __forceinline__ ull dup2(float v) { return pack2(v, v); }
__device__ __forceinline__ void fma2(ull& acc, ull a, ull b) {
    asm("fma.rn.f32x2 %0, %1, %2, %0;" : "+l"(acc) : "l"(a), "l"(b));
}
__device__ __forceinline__ float2 unpack2(ull v) {
    float2 f;
    asm("mov.b64 {%0, %1}, %2;" : "=f"(f.x), "=f"(f.y) : "l"(v));
    return f;
}

// ---------------------------------------------------------------------------
// Fused GAT layer: one CTA per (t, block). 256 threads.
// STAGE 1: x = node_feats (FIN=24), W cached in smem, out -> g_h1
// STAGE 2: x = g_h1 (FIN=256), W streamed from L2,   out -> g_h2
// smem: [region: x (dead after GEMM) aliased with alpha] [h] [als|ald] [W sm1]
// ---------------------------------------------------------------------------
template <int FIN, int STAGE>
__global__ __launch_bounds__(256, 2)
void gat_kernel(const float* __restrict__ x_in,
                const float* __restrict__ W,
                const float* __restrict__ asrc,
                const float* __restrict__ adst,
                const float* __restrict__ bias)
{
    extern __shared__ float sm[];
    const int HSTRIDE = 260;                    // pad: even, float4-friendly
    const int REGION  = (32 * FIN > 4224) ? 32 * FIN : 4224;

    float* region = sm;                         // x tile, later alpha
    float* x_sm   = region;
    float* alpha  = region;                     // alias (x dead before alpha written)
    float* h_sm   = region + REGION;            // 32*260
    float* als    = h_sm + 32 * HSTRIDE;        // 128
    float* ald    = als + 128;                  // 128
    float* W_sm   = ald + 128;                  // FIN*256 (stage 1 only)

    const int tid = threadIdx.x;
    const int t   = blockIdx.x / Bn;
    const int bb  = blockIdx.x % Bn;

    const float* xsrc = (STAGE == 1) ? x_in : g_h1;
    float*       outp = (STAGE == 1) ? g_h1 : g_h2;
    const float* xblk = xsrc + ((size_t)t * Nn + (size_t)bb * An) * FIN;

    // load x tile (coalesced)
    if (STAGE == 2) {
        const float4* src4 = reinterpret_cast<const float4*>(xblk);
        float4* dst4 = reinterpret_cast<float4*>(x_sm);
        #pragma unroll
        for (int i = 0; i < (32 * FIN) / 4; i += 256) dst4[i + tid] = src4[i + tid];
    } else {
        for (int i = tid; i < 32 * FIN; i += 256) x_sm[i] = xblk[i];
        for (int i = tid; i < (FIN * Dd) / 4; i += 256)
            reinterpret_cast<float4*>(W_sm)[i] = reinterpret_cast<const float4*>(W)[i];
    }
    __syncthreads();

    // ---- h = x @ W, packed over adjacent column pairs ----
    // thread: rows r0..r0+7, col pairs (2cp, 2cp+1) and (2cp+128, 2cp+129)
    {
        const int cp = tid & 63;
        const int r0 = (tid >> 6) * 8;

        ull acc0[8], acc1[8];
        #pragma unroll
        for (int i = 0; i < 8; i++) { acc0[i] = 0ull; acc1[i] = 0ull; }

        #pragma unroll 2
        for (int k = 0; k < FIN; k++) {
            ull w0, w1;
            if (STAGE == 1) {
                const ull* Wrow = reinterpret_cast<const ull*>(&W_sm[k * Dd]);
                w0 = Wrow[cp]; w1 = Wrow[cp + 64];
            } else {
                const ull* Wrow = reinterpret_cast<const ull*>(W + (size_t)k * Dd);
                w0 = Wrow[cp]; w1 = Wrow[cp + 64];
            }
            ull xd[8];
            #pragma unroll
            for (int i = 0; i < 8; i++) xd[i] = dup2(x_sm[(r0 + i) * FIN + k]);
            #pragma unroll
            for (int i = 0; i < 8; i++) {
                fma2(acc0[i], xd[i], w0);
                fma2(acc1[i], xd[i], w1);
            }
        }
        ull* h64 = reinterpret_cast<ull*>(h_sm);
        #pragma unroll
        for (int i = 0; i < 8; i++) {
            h64[(r0 + i) * (HSTRIDE / 2) + cp]      = acc0[i];
            h64[(r0 + i) * (HSTRIDE / 2) + cp + 64] = acc1[i];
        }
    }
    __syncthreads();

    // ---- attention logits per (node, head) ----
    if (tid < 128) {
        const int r = tid & 31;
        const int head = tid >> 5;
        const float* hrow = &h_sm[r * HSTRIDE + head * DHh];
        const float* as = &asrc[head * DHh];
        const float* ad = &adst[head * DHh];
        float s1 = 0.f, s2 = 0.f;
        #pragma unroll 8
        for (int j = 0; j < DHh; j++) {
            float hv = hrow[j];
            s1 = fmaf(hv, as[j], s1);
            s2 = fmaf(hv, ad[j], s2);
        }
        als[head * 32 + r] = s1;
        ald[head * 32 + r] = s2;
    }
    __syncthreads();

    // ---- softmax per (dst d, head) over 32 srcs (writes alpha over dead x) ----
    if (tid < 128) {
        const int d = tid & 31;
        const int head = tid >> 5;
        float* arow = &alpha[head * (32 * 33) + d * 33];
        const float adv = ald[head * 32 + d];
        float m = -1e30f;
        #pragma unroll
        for (int s = 0; s < 32; s++) {
            float e = als[head * 32 + s] + adv;
            e = (e >= 0.f) ? e : 0.2f * e;      // leaky_relu 0.2
            arow[s] = e;
            m = fmaxf(m, e);
        }
        float z = 0.f;
        #pragma unroll
        for (int s = 0; s < 32; s++) {
            float p = expf(arow[s] - m);
            arow[s] = p;
            z += p;
        }
        const float inv = 1.f / (z + 1e-16f);
        #pragma unroll
        for (int s = 0; s < 32; s++) arow[s] *= inv;
    }
    __syncthreads();

    // ---- aggregation: out[d, c] = sum_s alpha[head][d][s] * h[s][c] ----
    // thread: one head, 8 dst rows, 2 col pairs WITHIN the same head
    // (alpha dup reused for both packed FMAs)
    {
        const int head = tid >> 6;
        const int lane = tid & 63;
        const int cpl  = lane & 15;             // col-pair-local within head
        const int d0   = (lane >> 4) * 8;

        const ull* h64 = reinterpret_cast<const ull*>(h_sm);
        const float* arow = &alpha[head * (32 * 33)];

        ull acc0[8], acc1[8];
        #pragma unroll
        for (int i = 0; i < 8; i++) { acc0[i] = 0ull; acc1[i] = 0ull; }

        #pragma unroll 4
        for (int s = 0; s < 32; s++) {
            ull hv0 = h64[s * (HSTRIDE / 2) + head * 32 + cpl];
            ull hv1 = h64[s * (HSTRIDE / 2) + head * 32 + cpl + 16];
            #pragma unroll
            for (int dd = 0; dd < 8; dd++) {
                ull a = dup2(arow[(d0 + dd) * 33 + s]);
                fma2(acc0[dd], a, hv0);
                fma2(acc1[dd], a, hv1);
            }
        }

        const int c0 = head * 64 + 2 * cpl;
        const int c1 = c0 + 32;
        float2 bv0 = *reinterpret_cast<const float2*>(&bias[c0]);
        float2 bv1 = *reinterpret_cast<const float2*>(&bias[c1]);
        float* outblk = outp + ((size_t)t * Nn + (size_t)bb * An) * Dd;

        #pragma unroll
        for (int dd = 0; dd < 8; dd++) {
            float2 o0 = unpack2(acc0[dd]);
            float2 o1 = unpack2(acc1[dd]);
            o0.x = fmaxf(o0.x + bv0.x, 0.f);
            o0.y = fmaxf(o0.y + bv0.y, 0.f);
            o1.x = fmaxf(o1.x + bv1.x, 0.f);
            o1.y = fmaxf(o1.y + bv1.y, 0.f);
            *reinterpret_cast<float2*>(&outblk[(d0 + dd) * Dd + c0]) = o0;
            *reinterpret_cast<float2*>(&outblk[(d0 + dd) * Dd + c1]) = o1;
        }
    }
}

// ---------------------------------------------------------------------------
// Transformer over T=5 (last query row only) + output heads. One CTA per b.
// ---------------------------------------------------------------------------
__global__ __launch_bounds__(256)
void head_kernel(const float* __restrict__ wq, const float* __restrict__ bq,
                 const float* __restrict__ wk, const float* __restrict__ bk,
                 const float* __restrict__ wv, const float* __restrict__ bv,
                 const float* __restrict__ wo, const float* __restrict__ bo,
                 const float* __restrict__ lm_w, const float* __restrict__ lm_b,
                 const float* __restrict__ lv_w, const float* __restrict__ lv_b,
                 const float* __restrict__ ap_w, const float* __restrict__ ap_b,
                 const float* __restrict__ bh_w, const float* __restrict__ bh_b,
                 float* __restrict__ out)
{
    __shared__ float seq[Tt][Dd];
    __shared__ float ksm[Tt][Dd];
    __shared__ float vsm[Tt][Dd];
    __shared__ float qsm[Dd];
    __shared__ float ctx[Dd];
    __shared__ float feat[Dd];
    __shared__ float musm[Ll];
    __shared__ float attn[Hh][Tt];

    const int b = blockIdx.x;
    const int tid = threadIdx.x;
    const int c = tid;

    #pragma unroll
    for (int t = 0; t < Tt; t++)
        seq[t][tid] = g_h2[((size_t)t * Nn + (size_t)b * An) * Dd + tid];
    __syncthreads();

    {
        float aq = 0.f;
        float ak[Tt] = {0, 0, 0, 0, 0};
        float av[Tt] = {0, 0, 0, 0, 0};
        #pragma unroll 4
        for (int k = 0; k < Dd; k++) {
            float wqv = wq[(size_t)k * Dd + c];
            float wkv = wk[(size_t)k * Dd + c];
            float wvv = wv[(size_t)k * Dd + c];
            aq = fmaf(seq[Tt - 1][k], wqv, aq);
            #pragma unroll
            for (int t = 0; t < Tt; t++) {
                float sv = seq[t][k];
                ak[t] = fmaf(sv, wkv, ak[t]);
                av[t] = fmaf(sv, wvv, av[t]);
            }
        }
        qsm[c] = aq + bq[c];
        #pragma unroll
        for (int t = 0; t < Tt; t++) {
            ksm[t][c] = ak[t] + bk[c];
            vsm[t][c] = av[t] + bv[c];
        }
    }
    __syncthreads();

    if (tid < Hh * Tt) {
        const int head = tid / Tt;
        const int t = tid % Tt;
        float s = 0.f;
        #pragma unroll 8
        for (int j = 0; j < DHh; j++)
            s = fmaf(qsm[head * DHh + j], ksm[t][head * DHh + j], s);
        attn[head][t] = s * 0.125f;
    }
    __syncthreads();

    if (tid < Hh) {
        float m = -1e30f;
        #pragma unroll
        for (int t = 0; t < Tt; t++) m = fmaxf(m, attn[tid][t]);
        float z = 0.f;
        #pragma unroll
        for (int t = 0; t < Tt; t++) { float p = expf(attn[tid][t] - m); attn[tid][t] = p; z += p; }
        float inv = 1.f / z;
        #pragma unroll
        for (int t = 0; t < Tt; t++) attn[tid][t] *= inv;
    }
    __syncthreads();

    {
        const int head = c >> 6;
        float a = 0.f;
        #pragma unroll
        for (int t = 0; t < Tt; t++) a = fmaf(attn[head][t], vsm[t][c], a);
        ctx[c] = a;
    }
    __syncthreads();

    {
        float f = bo[c];
        #pragma unroll 4
        for (int k = 0; k < Dd; k++) f = fmaf(ctx[k], wo[(size_t)k * Dd + c], f);
        feat[c] = f;
    }
    __syncthreads();

    float* ob = out + (size_t)b * 400;

    if (tid < 64) {
        float m = lm_b[tid];
        #pragma unroll 4
        for (int k = 0; k < Dd; k++) m = fmaf(feat[k], lm_w[(size_t)k * Ll + tid], m);
        musm[tid] = m;
        ob[tid] = m;
    } else if (tid < 128) {
        const int cc = tid - 64;
        float m = lv_b[cc];
        #pragma unroll 4
        for (int k = 0; k < Dd; k++) m = fmaf(feat[k], lv_w[(size_t)k * Ll + cc], m);
        ob[64 + cc] = m;
    } else if (tid < 144) {
        const int cc = tid - 128;
        float m = bh_b[cc];
        #pragma unroll 4
        for (int k = 0; k < Dd; k++) m = fmaf(feat[k], bh_w[(size_t)k * 16 + cc], m);
        ob[384 + cc] = m;
    }
    __syncthreads();

    {
        float a = ap_b[c];
        #pragma unroll 8
        for (int k = 0; k < Ll; k++) a = fmaf(musm[k], ap_w[(size_t)k * Dd + c], a);
        ob[128 + c] = a;
    }
}

// ---------------------------------------------------------------------------
extern "C" void kernel_launch(void* const* d_in, const int* in_sizes, int n_in,
                              void* d_out, int out_size)
{
    const float* node_feats = (const float*)d_in[0];
    const float* gat1_w  = (const float*)d_in[2];
    const float* gat1_as = (const float*)d_in[3];
    const float* gat1_ad = (const float*)d_in[4];
    const float* gat1_b  = (const float*)d_in[5];
    const float* gat2_w  = (const float*)d_in[6];
    const float* gat2_as = (const float*)d_in[7];
    const float* gat2_ad = (const float*)d_in[8];
    const float* gat2_b  = (const float*)d_in[9];
    const float* wq = (const float*)d_in[10];
    const float* bq = (const float*)d_in[11];
    const float* wk = (const float*)d_in[12];
    const float* bk = (const float*)d_in[13];
    const float* wv = (const float*)d_in[14];
    const float* bv = (const float*)d_in[15];
    const float* wo = (const float*)d_in[16];
    const float* bo = (const float*)d_in[17];
    const float* lm_w = (const float*)d_in[18];
    const float* lm_b = (const float*)d_in[19];
    const float* lv_w = (const float*)d_in[20];
    const float* lv_b = (const float*)d_in[21];
    const float* ap_w = (const float*)d_in[22];
    const float* ap_b = (const float*)d_in[23];
    const float* bh_w = (const float*)d_in[24];
    const float* bh_b = (const float*)d_in[25];
    float* out = (float*)d_out;

    // smem (floats): region(max(32*FIN,4224)) + h(8320) + als/ald(256) [+ W sm1]
    const size_t sm1 = (size_t)(4224 + 8320 + 256 + 24 * 256) * sizeof(float);  // 75776 B
    const size_t sm2 = (size_t)(8192 + 8320 + 256) * sizeof(float);             // 67072 B

    cudaFuncSetAttribute(gat_kernel<24, 1>,  cudaFuncAttributeMaxDynamicSharedMemorySize, (int)sm1);
    cudaFuncSetAttribute(gat_kernel<256, 2>, cudaFuncAttributeMaxDynamicSharedMemorySize, (int)sm2);

    gat_kernel<24, 1><<<Tt * Bn, 256, sm1>>>(node_feats, gat1_w, gat1_as, gat1_ad, gat1_b);
    gat_kernel<256, 2><<<Tt * Bn, 256, sm2>>>(nullptr, gat2_w, gat2_as, gat2_ad, gat2_b);
    head_kernel<<<Bn, 256>>>(wq, bq, wk, bk, wv, bv, wo, bo,
                             lm_w, lm_b, lv_w, lv_b, ap_w, ap_b, bh_w, bh_b, out);
}

// round 3
// speedup vs baseline: 1.3451x; 1.1619x over previous
#include <cuda_runtime.h>
#include <math.h>

#define An 32
#define Bn 128
#define Nn 4096
#define Tt 5
#define Hh 4
#define DHh 64
#define Dd 256
#define Ll 64
#define FIN1 24

typedef unsigned long long ull;

// ego features only: [T][B][D]
__device__ float g_ego[Tt * Bn * Dd];

// ---- packed f32x2 helpers (SASS FFMA2 path) ----
__device__ __forceinline__ ull pack2(float lo, float hi) {
    ull r; asm("mov.b64 %0, {%1, %2};" : "=l"(r) : "f"(lo), "f"(hi)); return r;
}
__device__ __forceinline__ ull dup2(float v) { return pack2(v, v); }
__device__ __forceinline__ void fma2(ull& acc, ull a, ull b) {
    asm("fma.rn.f32x2 %0, %1, %2, %0;" : "+l"(acc) : "l"(a), "l"(b));
}
__device__ __forceinline__ float2 unpack2(ull v) {
    float2 f; asm("mov.b64 {%0, %1}, %2;" : "=f"(f.x), "=f"(f.y) : "l"(v)); return f;
}

// smem layout (floats)
#define REGION_OFF   0          // x1 [0,768) + W1 [768,6912); later alpha1 [0,4224)
#define H_OFF        6912       // h: 32*260
#define X2_OFF       15232      // x2: 32*256
#define ALS_OFF      23424      // 128
#define ALD_OFF      23552      // 128
#define A2_OFF       23680      // alpha2: 4*33 = 132
#define SM_FLOATS    23816
#define HSTRIDE      260

// ---------------------------------------------------------------------------
// Fully fused 2-layer GAT per (t, block). 256 threads, 2 CTAs/SM.
// Output: only ego (local node 0) features -> g_ego.
// ---------------------------------------------------------------------------
__global__ __launch_bounds__(256, 2)
void gnn_fused_kernel(const float* __restrict__ node_feats,
                      const float* __restrict__ W1,
                      const float* __restrict__ a1s, const float* __restrict__ a1d,
                      const float* __restrict__ b1,
                      const float* __restrict__ W2,
                      const float* __restrict__ a2s, const float* __restrict__ a2d,
                      const float* __restrict__ b2)
{
    extern __shared__ float sm[];
    float* x1_sm  = sm + REGION_OFF;
    float* W1_sm  = sm + REGION_OFF + 32 * FIN1;
    float* alpha1 = sm + REGION_OFF;            // alias over x1/W1 (dead)
    float* h_sm   = sm + H_OFF;
    float* x2_sm  = sm + X2_OFF;
    float* als    = sm + ALS_OFF;
    float* ald    = sm + ALD_OFF;
    float* alpha2 = sm + A2_OFF;

    const int tid = threadIdx.x;
    const int t   = blockIdx.x / Bn;
    const int bb  = blockIdx.x % Bn;

    // ---- load x1 tile + W1 ----
    {
        const float* xblk = node_feats + ((size_t)t * Nn + (size_t)bb * An) * FIN1;
        for (int i = tid; i < 32 * FIN1; i += 256) x1_sm[i] = xblk[i];
        const float4* Wsrc = reinterpret_cast<const float4*>(W1);
        float4* Wdst = reinterpret_cast<float4*>(W1_sm);
        #pragma unroll
        for (int i = 0; i < (FIN1 * Dd) / 4; i += 256) Wdst[i + tid] = Wsrc[i + tid];
    }
    __syncthreads();

    const int cp = tid & 63;
    const int r0 = (tid >> 6) * 8;

    // ============ GEMM1: h = x1 @ W1 (32 x 24 x 256) ============
    {
        ull acc0[8], acc1[8];
        #pragma unroll
        for (int i = 0; i < 8; i++) { acc0[i] = 0ull; acc1[i] = 0ull; }

        #pragma unroll
        for (int k = 0; k < FIN1; k += 2) {
            float2 xv[8];
            #pragma unroll
            for (int i = 0; i < 8; i++)
                xv[i] = *reinterpret_cast<const float2*>(&x1_sm[(r0 + i) * FIN1 + k]);
            {
                const ull* Wr = reinterpret_cast<const ull*>(&W1_sm[k * Dd]);
                ull w0 = Wr[cp], w1 = Wr[cp + 64];
                #pragma unroll
                for (int i = 0; i < 8; i++) {
                    ull d = dup2(xv[i].x);
                    fma2(acc0[i], d, w0); fma2(acc1[i], d, w1);
                }
            }
            {
                const ull* Wr = reinterpret_cast<const ull*>(&W1_sm[(k + 1) * Dd]);
                ull w0 = Wr[cp], w1 = Wr[cp + 64];
                #pragma unroll
                for (int i = 0; i < 8; i++) {
                    ull d = dup2(xv[i].y);
                    fma2(acc0[i], d, w0); fma2(acc1[i], d, w1);
                }
            }
        }
        ull* h64 = reinterpret_cast<ull*>(h_sm);
        #pragma unroll
        for (int i = 0; i < 8; i++) {
            h64[(r0 + i) * (HSTRIDE / 2) + cp]      = acc0[i];
            h64[(r0 + i) * (HSTRIDE / 2) + cp + 64] = acc1[i];
        }
    }
    __syncthreads();

    // ---- logits1 ----
    if (tid < 128) {
        const int r = tid & 31, head = tid >> 5;
        const float* hrow = &h_sm[r * HSTRIDE + head * DHh];
        const float* as = &a1s[head * DHh];
        const float* ad = &a1d[head * DHh];
        float s1 = 0.f, s2 = 0.f;
        #pragma unroll 8
        for (int j = 0; j < DHh; j++) {
            float hv = hrow[j];
            s1 = fmaf(hv, as[j], s1);
            s2 = fmaf(hv, ad[j], s2);
        }
        als[head * 32 + r] = s1;
        ald[head * 32 + r] = s2;
    }
    __syncthreads();

    // ---- softmax1: all dst (writes alpha1 over dead x1/W1) ----
    if (tid < 128) {
        const int d = tid & 31, head = tid >> 5;
        float* arow = &alpha1[head * (32 * 33) + d * 33];
        const float adv = ald[head * 32 + d];
        float m = -1e30f;
        #pragma unroll
        for (int s = 0; s < 32; s++) {
            float e = als[head * 32 + s] + adv;
            e = (e >= 0.f) ? e : 0.2f * e;
            arow[s] = e;
            m = fmaxf(m, e);
        }
        float z = 0.f;
        #pragma unroll
        for (int s = 0; s < 32; s++) { float p = expf(arow[s] - m); arow[s] = p; z += p; }
        const float inv = 1.f / (z + 1e-16f);
        #pragma unroll
        for (int s = 0; s < 32; s++) arow[s] *= inv;
    }
    __syncthreads();

    // ---- aggregation1 + bias + relu -> x2 ----
    {
        const int head = tid >> 6;
        const int lane = tid & 63;
        const int cpl  = lane & 15;
        const int d0   = (lane >> 4) * 8;

        const ull* h64 = reinterpret_cast<const ull*>(h_sm);
        const float* arow = &alpha1[head * (32 * 33)];

        ull acc0[8], acc1[8];
        #pragma unroll
        for (int i = 0; i < 8; i++) { acc0[i] = 0ull; acc1[i] = 0ull; }

        #pragma unroll 4
        for (int s = 0; s < 32; s++) {
            ull hv0 = h64[s * (HSTRIDE / 2) + head * 32 + cpl];
            ull hv1 = h64[s * (HSTRIDE / 2) + head * 32 + cpl + 16];
            #pragma unroll
            for (int dd = 0; dd < 8; dd++) {
                ull a = dup2(arow[(d0 + dd) * 33 + s]);
                fma2(acc0[dd], a, hv0);
                fma2(acc1[dd], a, hv1);
            }
        }

        const int c0 = head * 64 + 2 * cpl;
        const int c1 = c0 + 32;
        float2 bv0 = *reinterpret_cast<const float2*>(&b1[c0]);
        float2 bv1 = *reinterpret_cast<const float2*>(&b1[c1]);
        #pragma unroll
        for (int dd = 0; dd < 8; dd++) {
            float2 o0 = unpack2(acc0[dd]);
            float2 o1 = unpack2(acc1[dd]);
            o0.x = fmaxf(o0.x + bv0.x, 0.f);
            o0.y = fmaxf(o0.y + bv0.y, 0.f);
            o1.x = fmaxf(o1.x + bv1.x, 0.f);
            o1.y = fmaxf(o1.y + bv1.y, 0.f);
            *reinterpret_cast<float2*>(&x2_sm[(d0 + dd) * Dd + c0]) = o0;
            *reinterpret_cast<float2*>(&x2_sm[(d0 + dd) * Dd + c1]) = o1;
        }
    }
    __syncthreads();

    // ============ GEMM2: h2 = x2 @ W2 (32 x 256 x 256), W2 streamed from L2 ============
    {
        ull acc0[8], acc1[8];
        #pragma unroll
        for (int i = 0; i < 8; i++) { acc0[i] = 0ull; acc1[i] = 0ull; }

        #pragma unroll 2
        for (int k = 0; k < Dd; k += 2) {
            float2 xv[8];
            #pragma unroll
            for (int i = 0; i < 8; i++)
                xv[i] = *reinterpret_cast<const float2*>(&x2_sm[(r0 + i) * Dd + k]);
            {
                const ull* Wr = reinterpret_cast<const ull*>(W2 + (size_t)k * Dd);
                ull w0 = __ldg(&Wr[cp]), w1 = __ldg(&Wr[cp + 64]);
                #pragma unroll
                for (int i = 0; i < 8; i++) {
                    ull d = dup2(xv[i].x);
                    fma2(acc0[i], d, w0); fma2(acc1[i], d, w1);
                }
            }
            {
                const ull* Wr = reinterpret_cast<const ull*>(W2 + (size_t)(k + 1) * Dd);
                ull w0 = __ldg(&Wr[cp]), w1 = __ldg(&Wr[cp + 64]);
                #pragma unroll
                for (int i = 0; i < 8; i++) {
                    ull d = dup2(xv[i].y);
                    fma2(acc0[i], d, w0); fma2(acc1[i], d, w1);
                }
            }
        }
        ull* h64 = reinterpret_cast<ull*>(h_sm);
        #pragma unroll
        for (int i = 0; i < 8; i++) {
            h64[(r0 + i) * (HSTRIDE / 2) + cp]      = acc0[i];
            h64[(r0 + i) * (HSTRIDE / 2) + cp + 64] = acc1[i];
        }
    }
    __syncthreads();

    // ---- logits2 ----
    if (tid < 128) {
        const int r = tid & 31, head = tid >> 5;
        const float* hrow = &h_sm[r * HSTRIDE + head * DHh];
        const float* as = &a2s[head * DHh];
        const float* ad = &a2d[head * DHh];
        float s1 = 0.f, s2 = 0.f;
        #pragma unroll 8
        for (int j = 0; j < DHh; j++) {
            float hv = hrow[j];
            s1 = fmaf(hv, as[j], s1);
            s2 = fmaf(hv, ad[j], s2);
        }
        als[head * 32 + r] = s1;
        ald[head * 32 + r] = s2;       // only head*32+0 used below
    }
    __syncthreads();

    // ---- softmax2: dst = 0 only ----
    if (tid < 4) {
        const float adv = ald[tid * 32];
        float* arow = &alpha2[tid * 33];
        float m = -1e30f;
        #pragma unroll
        for (int s = 0; s < 32; s++) {
            float e = als[tid * 32 + s] + adv;
            e = (e >= 0.f) ? e : 0.2f * e;
            arow[s] = e;
            m = fmaxf(m, e);
        }
        float z = 0.f;
        #pragma unroll
        for (int s = 0; s < 32; s++) { float p = expf(arow[s] - m); arow[s] = p; z += p; }
        const float inv = 1.f / (z + 1e-16f);
        #pragma unroll
        for (int s = 0; s < 32; s++) arow[s] *= inv;
    }
    __syncthreads();

    // ---- aggregation2 (d=0) + bias + relu -> g_ego ----
    {
        const int c = tid;
        const int head = c >> 6;
        const float* arow = &alpha2[head * 33];
        float acc = 0.f;
        #pragma unroll 8
        for (int s = 0; s < 32; s++)
            acc = fmaf(arow[s], h_sm[s * HSTRIDE + c], acc);
        acc = fmaxf(acc + b2[c], 0.f);
        g_ego[((size_t)t * Bn + bb) * Dd + c] = acc;
    }
}

// ---------------------------------------------------------------------------
// Transformer over T=5 (last query row only) + output heads. One CTA per b.
// ---------------------------------------------------------------------------
__global__ __launch_bounds__(256)
void head_kernel(const float* __restrict__ wq, const float* __restrict__ bq,
                 const float* __restrict__ wk, const float* __restrict__ bk,
                 const float* __restrict__ wv, const float* __restrict__ bv,
                 const float* __restrict__ wo, const float* __restrict__ bo,
                 const float* __restrict__ lm_w, const float* __restrict__ lm_b,
                 const float* __restrict__ lv_w, const float* __restrict__ lv_b,
                 const float* __restrict__ ap_w, const float* __restrict__ ap_b,
                 const float* __restrict__ bh_w, const float* __restrict__ bh_b,
                 float* __restrict__ out)
{
    __shared__ float seq[Tt][Dd];
    __shared__ float ksm[Tt][Dd];
    __shared__ float vsm[Tt][Dd];
    __shared__ float qsm[Dd];
    __shared__ float ctx[Dd];
    __shared__ float feat[Dd];
    __shared__ float musm[Ll];
    __shared__ float attn[Hh][Tt];

    const int b = blockIdx.x;
    const int tid = threadIdx.x;
    const int c = tid;

    #pragma unroll
    for (int t = 0; t < Tt; t++)
        seq[t][tid] = g_ego[((size_t)t * Bn + b) * Dd + tid];
    __syncthreads();

    {
        float aq = 0.f;
        float ak[Tt] = {0, 0, 0, 0, 0};
        float av[Tt] = {0, 0, 0, 0, 0};
        #pragma unroll 4
        for (int k = 0; k < Dd; k++) {
            float wqv = wq[(size_t)k * Dd + c];
            float wkv = wk[(size_t)k * Dd + c];
            float wvv = wv[(size_t)k * Dd + c];
            aq = fmaf(seq[Tt - 1][k], wqv, aq);
            #pragma unroll
            for (int t = 0; t < Tt; t++) {
                float sv = seq[t][k];
                ak[t] = fmaf(sv, wkv, ak[t]);
                av[t] = fmaf(sv, wvv, av[t]);
            }
        }
        qsm[c] = aq + bq[c];
        #pragma unroll
        for (int t = 0; t < Tt; t++) {
            ksm[t][c] = ak[t] + bk[c];
            vsm[t][c] = av[t] + bv[c];
        }
    }
    __syncthreads();

    if (tid < Hh * Tt) {
        const int head = tid / Tt;
        const int t = tid % Tt;
        float s = 0.f;
        #pragma unroll 8
        for (int j = 0; j < DHh; j++)
            s = fmaf(qsm[head * DHh + j], ksm[t][head * DHh + j], s);
        attn[head][t] = s * 0.125f;
    }
    __syncthreads();

    if (tid < Hh) {
        float m = -1e30f;
        #pragma unroll
        for (int t = 0; t < Tt; t++) m = fmaxf(m, attn[tid][t]);
        float z = 0.f;
        #pragma unroll
        for (int t = 0; t < Tt; t++) { float p = expf(attn[tid][t] - m); attn[tid][t] = p; z += p; }
        float inv = 1.f / z;
        #pragma unroll
        for (int t = 0; t < Tt; t++) attn[tid][t] *= inv;
    }
    __syncthreads();

    {
        const int head = c >> 6;
        float a = 0.f;
        #pragma unroll
        for (int t = 0; t < Tt; t++) a = fmaf(attn[head][t], vsm[t][c], a);
        ctx[c] = a;
    }
    __syncthreads();

    {
        float f = bo[c];
        #pragma unroll 4
        for (int k = 0; k < Dd; k++) f = fmaf(ctx[k], wo[(size_t)k * Dd + c], f);
        feat[c] = f;
    }
    __syncthreads();

    float* ob = out + (size_t)b * 400;

    if (tid < 64) {
        float m = lm_b[tid];
        #pragma unroll 4
        for (int k = 0; k < Dd; k++) m = fmaf(feat[k], lm_w[(size_t)k * Ll + tid], m);
        musm[tid] = m;
        ob[tid] = m;
    } else if (tid < 128) {
        const int cc = tid - 64;
        float m = lv_b[cc];
        #pragma unroll 4
        for (int k = 0; k < Dd; k++) m = fmaf(feat[k], lv_w[(size_t)k * Ll + cc], m);
        ob[64 + cc] = m;
    } else if (tid < 144) {
        const int cc = tid - 128;
        float m = bh_b[cc];
        #pragma unroll 4
        for (int k = 0; k < Dd; k++) m = fmaf(feat[k], bh_w[(size_t)k * 16 + cc], m);
        ob[384 + cc] = m;
    }
    __syncthreads();

    {
        float a = ap_b[c];
        #pragma unroll 8
        for (int k = 0; k < Ll; k++) a = fmaf(musm[k], ap_w[(size_t)k * Dd + c], a);
        ob[128 + c] = a;
    }
}

// ---------------------------------------------------------------------------
extern "C" void kernel_launch(void* const* d_in, const int* in_sizes, int n_in,
                              void* d_out, int out_size)
{
    const float* node_feats = (const float*)d_in[0];
    const float* gat1_w  = (const float*)d_in[2];
    const float* gat1_as = (const float*)d_in[3];
    const float* gat1_ad = (const float*)d_in[4];
    const float* gat1_b  = (const float*)d_in[5];
    const float* gat2_w  = (const float*)d_in[6];
    const float* gat2_as = (const float*)d_in[7];
    const float* gat2_ad = (const float*)d_in[8];
    const float* gat2_b  = (const float*)d_in[9];
    const float* wq = (const float*)d_in[10];
    const float* bq = (const float*)d_in[11];
    const float* wk = (const float*)d_in[12];
    const float* bk = (const float*)d_in[13];
    const float* wv = (const float*)d_in[14];
    const float* bv = (const float*)d_in[15];
    const float* wo = (const float*)d_in[16];
    const float* bo = (const float*)d_in[17];
    const float* lm_w = (const float*)d_in[18];
    const float* lm_b = (const float*)d_in[19];
    const float* lv_w = (const float*)d_in[20];
    const float* lv_b = (const float*)d_in[21];
    const float* ap_w = (const float*)d_in[22];
    const float* ap_b = (const float*)d_in[23];
    const float* bh_w = (const float*)d_in[24];
    const float* bh_b = (const float*)d_in[25];
    float* out = (float*)d_out;

    const size_t smb = (size_t)SM_FLOATS * sizeof(float);   // ~95.3 KB
    cudaFuncSetAttribute(gnn_fused_kernel, cudaFuncAttributeMaxDynamicSharedMemorySize, (int)smb);

    gnn_fused_kernel<<<Tt * Bn, 256, smb>>>(node_feats,
                                            gat1_w, gat1_as, gat1_ad, gat1_b,
                                            gat2_w, gat2_as, gat2_ad, gat2_b);
    head_kernel<<<Bn, 256>>>(wq, bq, wk, bk, wv, bv, wo, bo,
                             lm_w, lm_b, lv_w, lv_b, ap_w, ap_b, bh_w, bh_b, out);
}